// round 6
// baseline (speedup 1.0000x reference)
#include <cuda_runtime.h>

// D2Q9 LBM single step, fused collide+stream+bounce-back+macro-lift.
//   f    [2048,2048,9]  f32
//   rho  [2048,2048]    f32
//   u    [2048,2048,2]  f32 (float2)
//   mask [2048,2048]    bool -> dtype UNKNOWN (u8 / i32 / f32): detected at runtime
//   out  [2048,2048,12] f32  (f_new[9], rho_new, ux, uy)
//
// jnp.roll(a, shift=e) => new[x,y] = old[x-ex, y-ey] (periodic, power-of-2 wrap).

#define NX 2048
#define NY 2048
#define WRAP(v) ((v) & 2047)

// ---- mask dtype detection state (device globals; no allocation) ----
__device__ unsigned int g_byte_flags[4];  // nonzero byte seen at offset%4==j
__device__ int          g_mask_mode;      // 0 = uint8, 1 = int32, 2 = float32

__global__ void reset_flags_kernel() {
    g_byte_flags[0] = g_byte_flags[1] = g_byte_flags[2] = g_byte_flags[3] = 0;
    g_mask_mode = 0;
}

// Scan first 4 MB of the mask buffer (safe for all candidate widths: the
// smallest possible allocation is 2048*2048*1 B = 4 MB).
__global__ void detect_mask_kernel(const unsigned int* __restrict__ mask_w) {
    const int nwords = (4 * 1024 * 1024) / 4;   // 1M uint32 words
    unsigned int loc[4] = {0, 0, 0, 0};
    for (int i = blockIdx.x * blockDim.x + threadIdx.x; i < nwords;
         i += gridDim.x * blockDim.x) {
        unsigned int w = mask_w[i];
        if (w) {
            if (w & 0x000000FFu) loc[0] = 1;
            if (w & 0x0000FF00u) loc[1] = 1;
            if (w & 0x00FF0000u) loc[2] = 1;
            if (w & 0xFF000000u) loc[3] = 1;
        }
    }
    #pragma unroll
    for (int j = 0; j < 4; j++)
        if (loc[j]) atomicOr(&g_byte_flags[j], 1u);
}

__global__ void resolve_mode_kernel() {
    bool f0 = g_byte_flags[0], f1 = g_byte_flags[1];
    bool f23 = g_byte_flags[2] | g_byte_flags[3];
    int mode;
    if (f1 || (f0 && f23)) mode = 0;      // bytes at %4==1 (or mixed) => 1-byte mask
    else if (f0)           mode = 1;      // only lowest byte => int32 value 1
    else if (f23)          mode = 2;      // only bytes 2,3 => float32 1.0f
    else                   mode = 0;      // no solids seen in window: any read works
    g_mask_mode = mode;
}

static __device__ __forceinline__ float bgk(float fs, float w, float r,
                                            float eu, float usq) {
    const float INV_TAU = 1.0f / 0.6f;
    float feq = w * r * (1.0f + 3.0f * eu + 4.5f * eu * eu - 1.5f * usq);
    return fs - (fs - feq) * INV_TAU;
}

__global__ __launch_bounds__(256)
void lbm_step_kernel(const float*  __restrict__ f,
                     const float*  __restrict__ rho,
                     const float2* __restrict__ u,
                     const void*   __restrict__ mask,
                     float* __restrict__ out)
{
    const int y = blockIdx.x * blockDim.x + threadIdx.x;   // contiguous dim
    const int x = blockIdx.y * blockDim.y + threadIdx.y;
    const int cell = x * NY + y;

    const int   EXq[9]  = {0, 1, 0, -1,  0, 1, -1, -1,  1};
    const int   EYq[9]  = {0, 0, 1,  0, -1, 1,  1, -1, -1};
    const float Wq[9]   = {4.0f/9.0f,
                           1.0f/9.0f, 1.0f/9.0f, 1.0f/9.0f, 1.0f/9.0f,
                           1.0f/36.0f, 1.0f/36.0f, 1.0f/36.0f, 1.0f/36.0f};
    const int   OPPq[9] = {0, 3, 4, 1, 2, 7, 8, 5, 6};

    // Interpret mask per detected dtype (g_mask_mode is uniform -> L2 broadcast)
    const int mode = g_mask_mode;
    bool solid;
    if (mode == 0)      solid = ((const unsigned char*)mask)[cell] != 0;
    else if (mode == 1) solid = ((const int*)mask)[cell] != 0;
    else                solid = ((const float*)mask)[cell] != 0.0f;

    float fn[9];

    if (solid) {
        // Bounce-back: f_new[i] = f_star[own cell, OPP[i]]
        const float  r   = rho[cell];
        const float2 uv  = u[cell];
        const float  usq = uv.x * uv.x + uv.y * uv.y;
        const float* fc  = f + (size_t)cell * 9;
        float fstar[9];
        #pragma unroll
        for (int i = 0; i < 9; i++) {
            float eu = (float)EXq[i] * uv.x + (float)EYq[i] * uv.y;
            fstar[i] = bgk(fc[i], Wq[i], r, eu, usq);
        }
        #pragma unroll
        for (int i = 0; i < 9; i++) fn[i] = fstar[OPPq[i]];
    } else {
        // Stream: pull collided component i from upstream neighbor
        #pragma unroll
        for (int i = 0; i < 9; i++) {
            const int xs = WRAP(x - EXq[i]);
            const int ys = WRAP(y - EYq[i]);
            const int sc = xs * NY + ys;
            const float  r  = rho[sc];
            const float2 uv = u[sc];
            const float eu  = (float)EXq[i] * uv.x + (float)EYq[i] * uv.y;
            const float usq = uv.x * uv.x + uv.y * uv.y;
            const float fs  = f[(size_t)sc * 9 + i];
            fn[i] = bgk(fs, Wq[i], r, eu, usq);
        }
    }

    // Macro fields from post-stream populations
    float rn = 0.0f;
    #pragma unroll
    for (int i = 0; i < 9; i++) rn += fn[i];
    const float uxn = (fn[1] - fn[3]) + (fn[5] - fn[6]) + (fn[8] - fn[7]);
    const float uyn = (fn[2] - fn[4]) + (fn[5] + fn[6]) - (fn[7] + fn[8]);
    const float inv_rn = 1.0f / rn;

    float4* op = reinterpret_cast<float4*>(out + (size_t)cell * 12);
    op[0] = make_float4(fn[0], fn[1], fn[2], fn[3]);
    op[1] = make_float4(fn[4], fn[5], fn[6], fn[7]);
    op[2] = make_float4(fn[8], rn, uxn * inv_rn, uyn * inv_rn);
}

extern "C" void kernel_launch(void* const* d_in, const int* in_sizes, int n_in,
                              void* d_out, int out_size)
{
    const float*  f    = (const float*)d_in[0];
    const float*  rho  = (const float*)d_in[1];
    const float2* u    = (const float2*)d_in[2];
    const void*   mask = d_in[3];
    float*        out  = (float*)d_out;

    reset_flags_kernel<<<1, 1>>>();
    detect_mask_kernel<<<256, 256>>>((const unsigned int*)mask);
    resolve_mode_kernel<<<1, 1>>>();

    dim3 block(32, 8);
    dim3 grid(NY / 32, NX / 8);
    lbm_step_kernel<<<grid, block>>>(f, rho, u, mask, out);
}

// round 7
// speedup vs baseline: 1.0201x; 1.0201x over previous
#include <cuda_runtime.h>

// D2Q9 LBM single step: smem-tiled collide-once + stream + bounce-back + macro.
//   f    [2048,2048,9]  f32
//   rho  [2048,2048]    f32
//   u    [2048,2048,2]  f32 (float2)
//   mask [2048,2048]    bool, dtype unknown (u8/i32/f32) -> detected at runtime
//   out  [2048,2048,12] f32  (f_new[9], rho_new, ux, uy)
//
// jnp.roll(a, shift=e) => new[x,y] = old[x-ex, y-ey] (periodic, &2047 wrap).

#define NXg 2048
#define NYg 2048
#define WRAP(v) ((v) & 2047)

#define TW 64   // tile width  (Y, contiguous dim)
#define TH 8    // tile height (X)
#define HW (TW + 2)
#define HH (TH + 2)
#define HCELLS (HW * HH)   // 660

// ---- mask dtype detection (zero-init at module load; atomicOr idempotent) ----
__device__ unsigned int g_byte_flags[4];

__global__ void detect_mask_kernel(const uint4* __restrict__ mask_v) {
    // Scan first 1 MB (in-bounds for the smallest candidate: u8 mask = 4 MB).
    const int nvec = (1024 * 1024) / 16;   // 65536 uint4
    unsigned int loc0 = 0, loc1 = 0, loc2 = 0, loc3 = 0;
    for (int i = blockIdx.x * blockDim.x + threadIdx.x; i < nvec;
         i += gridDim.x * blockDim.x) {
        uint4 v = mask_v[i];
        unsigned int w = v.x | v.y | v.z | v.w;
        if (w) {
            loc0 |= (w & 0x000000FFu);
            loc1 |= (w & 0x0000FF00u);
            loc2 |= (w & 0x00FF0000u);
            loc3 |= (w & 0xFF000000u);
        }
    }
    if (loc0) atomicOr(&g_byte_flags[0], 1u);
    if (loc1) atomicOr(&g_byte_flags[1], 1u);
    if (loc2) atomicOr(&g_byte_flags[2], 1u);
    if (loc3) atomicOr(&g_byte_flags[3], 1u);
}

static __device__ __forceinline__ float bgk(float fs, float w, float r,
                                            float eu, float usq) {
    const float INV_TAU = 1.0f / 0.6f;
    float feq = w * r * (1.0f + 3.0f * eu + 4.5f * eu * eu - 1.5f * usq);
    return fs - (fs - feq) * INV_TAU;
}

__global__ __launch_bounds__(256)
void lbm_step_kernel(const float*  __restrict__ f,
                     const float*  __restrict__ rho,
                     const float2* __restrict__ u,
                     const void*   __restrict__ mask,
                     float* __restrict__ out)
{
    __shared__ float fs[HH][HW][9];   // 660 * 9 * 4 B = 23.8 KB

    const int tid = threadIdx.x;
    const int Y0  = blockIdx.x * TW;
    const int X0  = blockIdx.y * TH;

    const int   EXq[9]  = {0, 1, 0, -1,  0, 1, -1, -1,  1};
    const int   EYq[9]  = {0, 0, 1,  0, -1, 1,  1, -1, -1};
    const float Wq[9]   = {4.0f/9.0f,
                           1.0f/9.0f, 1.0f/9.0f, 1.0f/9.0f, 1.0f/9.0f,
                           1.0f/36.0f, 1.0f/36.0f, 1.0f/36.0f, 1.0f/36.0f};
    const int   OPPq[9] = {0, 3, 4, 1, 2, 7, 8, 5, 6};

    // Resolve mask dtype from detection flags (uniform; 4 L2-broadcast loads)
    const bool f0  = g_byte_flags[0] != 0;
    const bool f1  = g_byte_flags[1] != 0;
    const bool f23 = (g_byte_flags[2] | g_byte_flags[3]) != 0;
    int mode;
    if (f1 || (f0 && f23)) mode = 0;       // 1-byte mask
    else if (f0)           mode = 1;       // int32
    else if (f23)          mode = 2;       // float32
    else                   mode = 0;       // no solids in window: any read works

    // ---- Phase 1: collide once per tile+halo cell, stash f_star in smem ----
    #pragma unroll
    for (int base = 0; base < HCELLS; base += 256) {
        const int idx = base + tid;
        if (idx < HCELLS) {
            const int hx = idx / HW;             // 0..9
            const int hy = idx - hx * HW;        // 0..65
            const int gx = WRAP(X0 + hx - 1);
            const int gy = WRAP(Y0 + hy - 1);
            const int sc = gx * NYg + gy;

            const float  r   = rho[sc];
            const float2 uv  = u[sc];
            const float  usq = uv.x * uv.x + uv.y * uv.y;
            const float* fc  = f + (size_t)sc * 9;

            float fv[9];
            #pragma unroll
            for (int i = 0; i < 9; i++) fv[i] = fc[i];
            #pragma unroll
            for (int i = 0; i < 9; i++) {
                const float eu = (float)EXq[i] * uv.x + (float)EYq[i] * uv.y;
                fs[hx][hy][i] = bgk(fv[i], Wq[i], r, eu, usq);
            }
        }
    }
    __syncthreads();

    // ---- Phase 2: stream-gather from smem, bounce-back, macro lift, store ----
    #pragma unroll
    for (int c = 0; c < 2; c++) {
        const int ly = tid & (TW - 1);           // 0..63
        const int lx = (tid >> 6) + c * 4;       // 0..7
        const int gx = X0 + lx;
        const int gy = Y0 + ly;
        const int cell = gx * NYg + gy;

        bool solid;
        if (mode == 0)      solid = ((const unsigned char*)mask)[cell] != 0;
        else if (mode == 1) solid = ((const int*)mask)[cell] != 0;
        else                solid = ((const float*)mask)[cell] != 0.0f;

        float fn[9];
        if (solid) {
            #pragma unroll
            for (int i = 0; i < 9; i++)
                fn[i] = fs[lx + 1][ly + 1][OPPq[i]];
        } else {
            #pragma unroll
            for (int i = 0; i < 9; i++)
                fn[i] = fs[lx + 1 - EXq[i]][ly + 1 - EYq[i]][i];
        }

        float rn = 0.0f;
        #pragma unroll
        for (int i = 0; i < 9; i++) rn += fn[i];
        const float uxn = (fn[1] - fn[3]) + (fn[5] - fn[6]) + (fn[8] - fn[7]);
        const float uyn = (fn[2] - fn[4]) + (fn[5] + fn[6]) - (fn[7] + fn[8]);
        const float inv_rn = 1.0f / rn;

        float4* op = reinterpret_cast<float4*>(out + (size_t)cell * 12);
        op[0] = make_float4(fn[0], fn[1], fn[2], fn[3]);
        op[1] = make_float4(fn[4], fn[5], fn[6], fn[7]);
        op[2] = make_float4(fn[8], rn, uxn * inv_rn, uyn * inv_rn);
    }
}

extern "C" void kernel_launch(void* const* d_in, const int* in_sizes, int n_in,
                              void* d_out, int out_size)
{
    const float*  f    = (const float*)d_in[0];
    const float*  rho  = (const float*)d_in[1];
    const float2* u    = (const float2*)d_in[2];
    const void*   mask = d_in[3];
    float*        out  = (float*)d_out;

    detect_mask_kernel<<<64, 256>>>((const uint4*)mask);

    dim3 block(256);
    dim3 grid(NYg / TW, NXg / TH);   // 32 x 256 = 8192 CTAs
    lbm_step_kernel<<<grid, block>>>(f, rho, u, mask, out);
}

// round 8
// speedup vs baseline: 1.0544x; 1.0336x over previous
#include <cuda_runtime.h>

// D2Q9 LBM single step, fused gather formulation with batched loads.
//   f    [2048,2048,9]  f32
//   rho  [2048,2048]    f32
//   u    [2048,2048,2]  f32 (float2)
//   mask [2048,2048]    bool, dtype unknown (u8/i32/f32) -> runtime detection
//   out  [2048,2048,12] f32  (f_new[9], rho_new, ux, uy)
//
// jnp.roll(a, shift=e) => new[x,y] = old[x-ex, y-ey] (periodic &2047).
// Bounce-back identity: f_new[i] = bgk(f[cell][OPP[i]], W[i], rho, -e_i.u, usq)
// so solid cells share the fluid pipeline with (src=self, comp=OPP, sign=-1).

#define NXg 2048
#define NYg 2048
#define WRAP(v) ((v) & 2047)

// ---- mask dtype detection (device globals zero-init; atomicOr idempotent) ----
__device__ unsigned int g_byte_flags[4];

__global__ void detect_mask_kernel(const uint4* __restrict__ mask_v) {
    // Scan first 256 KB (smallest candidate buffer is 4 MB; >=65k cells seen).
    const int nvec = (256 * 1024) / 16;
    unsigned int loc0 = 0, loc1 = 0, loc2 = 0, loc3 = 0;
    for (int i = blockIdx.x * blockDim.x + threadIdx.x; i < nvec;
         i += gridDim.x * blockDim.x) {
        uint4 v = mask_v[i];
        unsigned int w = v.x | v.y | v.z | v.w;
        loc0 |= (w & 0x000000FFu);
        loc1 |= (w & 0x0000FF00u);
        loc2 |= (w & 0x00FF0000u);
        loc3 |= (w & 0xFF000000u);
    }
    if (loc0) atomicOr(&g_byte_flags[0], 1u);
    if (loc1) atomicOr(&g_byte_flags[1], 1u);
    if (loc2) atomicOr(&g_byte_flags[2], 1u);
    if (loc3) atomicOr(&g_byte_flags[3], 1u);
}

__global__ __launch_bounds__(256, 4)
void lbm_step_kernel(const float*  __restrict__ f,
                     const float*  __restrict__ rho,
                     const float2* __restrict__ u,
                     const void*   __restrict__ mask,
                     float* __restrict__ out)
{
    const int y = blockIdx.x * 32 + (threadIdx.x & 31);   // contiguous dim
    const int x = blockIdx.y * 8  + (threadIdx.x >> 5);
    const unsigned int cell = (unsigned int)x * NYg + y;

    const int   EXq[9]  = {0, 1, 0, -1,  0, 1, -1, -1,  1};
    const int   EYq[9]  = {0, 0, 1,  0, -1, 1,  1, -1, -1};
    const float Wq[9]   = {4.0f/9.0f,
                           1.0f/9.0f, 1.0f/9.0f, 1.0f/9.0f, 1.0f/9.0f,
                           1.0f/36.0f, 1.0f/36.0f, 1.0f/36.0f, 1.0f/36.0f};
    const int   OPPq[9] = {0, 3, 4, 1, 2, 7, 8, 5, 6};

    // Resolve mask dtype from detection flags (uniform loads, L2 broadcast)
    const bool b0  = g_byte_flags[0] != 0;
    const bool b1  = g_byte_flags[1] != 0;
    const bool b23 = (g_byte_flags[2] | g_byte_flags[3]) != 0;
    int mode;
    if (b1 || (b0 && b23)) mode = 0;       // 1-byte mask
    else if (b0)           mode = 1;       // int32
    else if (b23)          mode = 2;       // float32
    else                   mode = 0;       // no solids in window: any read works

    bool solid;
    if (mode == 0)      solid = ((const unsigned char*)mask)[cell] != 0;
    else if (mode == 1) solid = ((const int*)mask)[cell] != 0;
    else                solid = ((const float*)mask)[cell] != 0.0f;

    // ---- source indices (branchless solid handling) ----
    unsigned int sc[9];     // source cell
    unsigned int fo[9];     // f element offset = sc*9 + comp
    #pragma unroll
    for (int i = 0; i < 9; i++) {
        const int xs = solid ? x : WRAP(x - EXq[i]);
        const int ys = solid ? y : WRAP(y - EYq[i]);
        const int ci = solid ? OPPq[i] : i;
        sc[i] = (unsigned int)xs * NYg + ys;
        fo[i] = sc[i] * 9u + ci;
    }

    // ---- batched loads: 9 f + 9 u(float2) + 9 rho, all independent ----
    float  fv[9];
    #pragma unroll
    for (int i = 0; i < 9; i++) fv[i] = f[fo[i]];
    float2 uvv[9];
    #pragma unroll
    for (int i = 0; i < 9; i++) uvv[i] = u[sc[i]];
    float  rv[9];
    #pragma unroll
    for (int i = 0; i < 9; i++) rv[i] = rho[sc[i]];

    // ---- collide (BGK) at each source ----
    const float sgn = solid ? -1.0f : 1.0f;
    const float INV_TAU = 1.0f / 0.6f;
    float fn[9];
    #pragma unroll
    for (int i = 0; i < 9; i++) {
        const float ux = uvv[i].x, uy = uvv[i].y;
        const float eu  = sgn * ((float)EXq[i] * ux + (float)EYq[i] * uy);
        const float usq = ux * ux + uy * uy;
        const float feq = Wq[i] * rv[i] *
                          (1.0f + 3.0f * eu + 4.5f * eu * eu - 1.5f * usq);
        fn[i] = fv[i] - (fv[i] - feq) * INV_TAU;
    }

    // ---- macro lift ----
    float rn = 0.0f;
    #pragma unroll
    for (int i = 0; i < 9; i++) rn += fn[i];
    const float uxn = (fn[1] - fn[3]) + (fn[5] - fn[6]) + (fn[8] - fn[7]);
    const float uyn = (fn[2] - fn[4]) + (fn[5] + fn[6]) - (fn[7] + fn[8]);
    const float inv_rn = 1.0f / rn;

    float4* op = reinterpret_cast<float4*>(out + (size_t)cell * 12);
    op[0] = make_float4(fn[0], fn[1], fn[2], fn[3]);
    op[1] = make_float4(fn[4], fn[5], fn[6], fn[7]);
    op[2] = make_float4(fn[8], rn, uxn * inv_rn, uyn * inv_rn);
}

extern "C" void kernel_launch(void* const* d_in, const int* in_sizes, int n_in,
                              void* d_out, int out_size)
{
    const float*  f    = (const float*)d_in[0];
    const float*  rho  = (const float*)d_in[1];
    const float2* u    = (const float2*)d_in[2];
    const void*   mask = d_in[3];
    float*        out  = (float*)d_out;

    detect_mask_kernel<<<32, 256>>>((const uint4*)mask);

    dim3 block(256);
    dim3 grid(NYg / 32, NXg / 8);   // 64 x 256 = 16384 CTAs
    lbm_step_kernel<<<grid, block>>>(f, rho, u, mask, out);
}